// round 1
// baseline (speedup 1.0000x reference)
#include <cuda_runtime.h>

// out[b, idx] = prod_w ( bit_{19-w}(idx) ? sin(h[b,w]) : cos(h[b,w]) ),
// h = (x + params) * 0.5. Wire w <-> idx bit (19-w).
// hi = idx>>10 (bits 10..19 -> wires 9..0), lo = idx & 1023 (bits 0..9 -> wires 19..10).

#define N_WIRES 20
#define BATCH 64
#define HI_PER_BLOCK 16          // hi values per block
#define THREADS 256

__global__ __launch_bounds__(THREADS, 8)
void qansatz_kernel(const float* __restrict__ x,
                    const float* __restrict__ params,
                    float* __restrict__ out)
{
    __shared__ float sc[N_WIRES];    // cos per wire
    __shared__ float ss[N_WIRES];    // sin per wire
    __shared__ float t_lo[1024];     // product over wires 10..19
    __shared__ float p_hi[HI_PER_BLOCK];

    const int b       = blockIdx.y;          // batch
    const int hi_base = blockIdx.x * HI_PER_BLOCK;
    const int tid     = threadIdx.x;

    // 1) cos/sin for this batch's 20 wires
    if (tid < N_WIRES) {
        float h = (x[b * N_WIRES + tid] + params[tid]) * 0.5f;
        float c, s;
        sincosf(h, &s, &c);
        sc[tid] = c;
        ss[tid] = s;
    }
    __syncthreads();

    // 2) low-bits table: t_lo[lo] = prod_{q=0}^{9} (lo>>q & 1 ? ss[19-q] : sc[19-q])
    {
        int lo0 = tid;               // 256 threads, 4 entries each
        #pragma unroll
        for (int r = 0; r < 4; r++) {
            int lo = lo0 + r * 256;
            float p = 1.0f;
            #pragma unroll
            for (int q = 0; q < 10; q++) {
                p *= ((lo >> q) & 1) ? ss[19 - q] : sc[19 - q];
            }
            t_lo[lo] = p;
        }
    }

    // 3) hi products: p_hi[i] = prod_{q=0}^{9} (h>>q & 1 ? ss[9-q] : sc[9-q])
    if (tid < HI_PER_BLOCK) {
        int h = hi_base + tid;
        float p = 1.0f;
        #pragma unroll
        for (int q = 0; q < 10; q++) {
            p *= ((h >> q) & 1) ? ss[9 - q] : sc[9 - q];
        }
        p_hi[tid] = p;
    }
    __syncthreads();

    // 4) stream out: for each hi, 256 threads x float4 = 1024 floats
    size_t base = ((size_t)b << 20) + ((size_t)hi_base << 10);
    const float4* t4 = reinterpret_cast<const float4*>(t_lo);
    float4 lo4 = t4[tid];            // each thread's 4 lo-values (reused for all 16 hi)

    #pragma unroll
    for (int i = 0; i < HI_PER_BLOCK; i++) {
        float ph = p_hi[i];
        float4 v;
        v.x = ph * lo4.x;
        v.y = ph * lo4.y;
        v.z = ph * lo4.z;
        v.w = ph * lo4.w;
        float4* dst = reinterpret_cast<float4*>(out + base + ((size_t)i << 10)) + tid;
        __stcs(dst, v);              // streaming store: write-once output
    }
}

extern "C" void kernel_launch(void* const* d_in, const int* in_sizes, int n_in,
                              void* d_out, int out_size)
{
    const float* x      = (const float*)d_in[0];   // (64, 20)
    const float* params = (const float*)d_in[1];   // (20,)
    float* out          = (float*)d_out;           // (64, 2^20)

    dim3 grid(1024 / HI_PER_BLOCK, BATCH);         // (64, 64)
    qansatz_kernel<<<grid, THREADS>>>(x, params, out);
}